// round 13
// baseline (speedup 1.0000x reference)
#include <cuda_runtime.h>
#include <cuda_fp16.h>
#include <math.h>
#include <stdint.h>

#define NT     256
#define NF     256
#define KD     128
#define NMAX   262144

#define INVD4  0.2973017787506803f    // 128^(-1/4)
#define HC     0.04419417382415922f   // 1/(2*sqrt(128))

#define BFF_U32 16384                 // B fragments (fp16): 64 KB
#define AFF_U32 4096                  // A fragments (fp16, 64 phys rows): 16 KB

// ---------------- globals -------------------------------------------------------
static __device__ unsigned g_max_u;
static __device__ float    g_maxval;
static __device__ float    g_sumKraw[NF];
static __device__ float    g_sumK[NF];
static __device__ float    g_srow[NMAX];                 // per-row max of raw U_K
static __device__ __half2  g_E2[(size_t)NMAX * 128];     // exp(U_K - h - srow), frag order

__device__ __forceinline__ unsigned f2u(float f) {
    unsigned b = __float_as_uint(f);
    return (b & 0x80000000u) ? ~b : (b | 0x80000000u);
}
__device__ __forceinline__ float u2f(unsigned u) {
    return (u & 0x80000000u) ? __uint_as_float(u ^ 0x80000000u) : __uint_as_float(~u);
}

__global__ void sp_init() {
    if (threadIdx.x == 0) g_max_u = 0u;
    g_sumKraw[threadIdx.x] = 0.f;
}
__global__ void sp_finalize(float neps) {
    const float gmax = u2f(g_max_u);
    if (threadIdx.x == 0) g_maxval = gmax;
    g_sumK[threadIdx.x] = (g_sumKraw[threadIdx.x] * expf(-gmax) + neps) * 0.0625f;
}

// ---------------- FMA-pipe exp (no MUFU) ----------------------------------------
// exp(x) for x <= 0, ~2e-6 rel err. Magic-constant range reduction + deg-5 Taylor
// for 2^f on [-0.5, 0.5]; exponent via integer add+shift. All fma/alu pipe.
__device__ __forceinline__ float fexp(float x) {
    const float L2E = 1.4426950408889634f;
    const float MAGIC = 12582912.0f;          // 1.5 * 2^23
    x = fmaxf(x, -87.0f);
    const float t = fmaf(x, L2E, MAGIC);      // int(n) in mantissa, round-to-nearest
    const float n = t - MAGIC;
    const float f = fmaf(x, L2E, -n);         // f in [-0.5, 0.5]
    float p = 1.3333558146e-3f;               // ln2^5/120
    p = fmaf(p, f, 9.6181291076e-3f);         // ln2^4/24
    p = fmaf(p, f, 5.5504108664e-2f);         // ln2^3/6
    p = fmaf(p, f, 2.4022650700e-1f);         // ln2^2/2
    p = fmaf(p, f, 6.9314718056e-1f);         // ln2
    p = fmaf(p, f, 1.0f);
    const int sbits = (__float_as_int(t) + (127 - 0x4B400000)) << 23;  // (n+127)<<23
    return p * __int_as_float(sbits);
}

// ---------------- fp16 mma machinery --------------------------------------------
__device__ __forceinline__ void mma_f16(float* d, const uint4& a, uint32_t b0, uint32_t b1) {
    asm volatile(
        "mma.sync.aligned.m16n8k16.row.col.f32.f16.f16.f32 "
        "{%0,%1,%2,%3}, {%4,%5,%6,%7}, {%8,%9}, {%0,%1,%2,%3};\n"
        : "+f"(d[0]), "+f"(d[1]), "+f"(d[2]), "+f"(d[3])
        : "r"(a.x), "r"(a.y), "r"(a.z), "r"(a.w), "r"(b0), "r"(b1));
}

__device__ __forceinline__ void load_B_h(const float* __restrict__ omg,
                                         uint32_t* __restrict__ Bff, int tid) {
    __half* Bh = (__half*)Bff;
    for (int i = tid; i < KD * NF; i += NT) {
        const int k = i >> 8, n = i & 255;
        const __half hv = __float2half(omg[i] * INVD4);
        const int np = n >> 3, npair = np >> 1, ks = k >> 4;
        const int lane = ((n & 7) << 2) | ((k & 7) >> 1);
        const int slot = ((np & 1) << 1) | ((k >> 3) & 1);
        const int u32idx = ((npair * 8 + ks) * 32 + lane) * 4 + slot;
        Bh[u32idx * 2 + (k & 1)] = hv;
    }
}

__device__ __forceinline__ void frag_store(uint32_t* __restrict__ Aff, int sr, int lane,
                                           const float4& v) {
    __half2 h01 = __floats2half2_rn(v.x, v.y);
    __half2 h23 = __floats2half2_rn(v.z, v.w);
    const int k0 = lane << 2;
    const int mi = sr >> 4, rlo = sr & 15, ks = k0 >> 4;
    const int reg = ((rlo >> 3) & 1) | (((k0 >> 3) & 1) << 1);
    const int ls  = ((rlo & 7) << 2) | ((k0 >> 1) & 3);
    uint32_t* base = Aff + (unsigned)((mi * 8 + ks) * 32) * 4 + reg;
    base[ls * 4]       = *(uint32_t*)&h01;
    base[(ls + 1) * 4] = *(uint32_t*)&h23;
}

// 64x256x128 GEMM, 8 warps, warp (wr,wc) owns 32 phys rows x 64 cols
__device__ __forceinline__ void gemm_tile(const uint4* __restrict__ Aff4,
                                          const uint4* __restrict__ Bff4,
                                          int wr, int wc, int lane, float acc[2][8][4]) {
#pragma unroll
    for (int i = 0; i < 2; i++)
#pragma unroll
        for (int j = 0; j < 8; j++)
#pragma unroll
            for (int c = 0; c < 4; c++) acc[i][j][c] = 0.f;
#pragma unroll
    for (int ks = 0; ks < 8; ks++) {
        uint4 a0 = Aff4[((wr * 2) * 8 + ks) * 32 + lane];
        uint4 a1 = Aff4[((wr * 2 + 1) * 8 + ks) * 32 + lane];
#pragma unroll
        for (int p = 0; p < 4; p++) {
            uint4 bv = Bff4[((wc * 4 + p) * 8 + ks) * 32 + lane];
            mma_f16(acc[0][2 * p],     a0, bv.x, bv.y);
            mma_f16(acc[0][2 * p + 1], a0, bv.z, bv.w);
            mma_f16(acc[1][2 * p],     a1, bv.x, bv.y);
            mma_f16(acc[1][2 * p + 1], a1, bv.z, bv.w);
        }
    }
}

__device__ __forceinline__ float grp_sum(float v) {
    v += __shfl_xor_sync(0xffffffffu, v, 1);
    v += __shfl_xor_sync(0xffffffffu, v, 2);
    return v;
}
__device__ __forceinline__ float grp_max(float v) {
    v = fmaxf(v, __shfl_xor_sync(0xffffffffu, v, 1));
    v = fmaxf(v, __shfl_xor_sync(0xffffffffu, v, 2));
    return v;
}

// ---------------- pass 1: U_K -> gmax, colsums, E' cache ------------------------
__global__ void __launch_bounds__(NT, 2)
sp_kpass(const float* __restrict__ Kg, const float* __restrict__ omg, int ntiles) {
    extern __shared__ float sh[];
    uint32_t* Bff = (uint32_t*)sh;
    uint32_t* Aff = Bff + BFF_U32;
    float* hrow  = (float*)(Aff + AFF_U32);  // 64
    float* cs    = hrow + 64;                // 256
    float* rmarr = cs + NF;                  // 256
    unsigned* bmax = (unsigned*)(rmarr + 256);

    const int tid = threadIdx.x, wid = tid >> 5, lane = tid & 31;
    const int wr = wid >> 2, wc = wid & 3;

    load_B_h(omg, Bff, tid);
    if (tid < NF) cs[tid] = 0.f;
    if (tid == 0) *bmax = 0u;
    __syncthreads();

    float acc[2][8][4];
    for (int tile = blockIdx.x; tile < ntiles; tile += gridDim.x) {
        const size_t row0 = (size_t)tile * 64;
#pragma unroll
        for (int t = 0; t < 8; t++) {
            const int i = tid + t * NT;
            const int sr = i >> 5;
            float4 v = *(const float4*)(Kg + (row0 + sr) * KD + (lane << 2));
            float p = v.x * v.x + v.y * v.y + v.z * v.z + v.w * v.w;
#pragma unroll
            for (int o = 16; o; o >>= 1) p += __shfl_xor_sync(0xffffffffu, p, o);
            if (lane == 0) hrow[sr] = p * HC;
            frag_store(Aff, sr, lane, v);
        }
        __syncthreads();
        gemm_tile((const uint4*)Aff, (const uint4*)Bff, wr, wc, lane, acc);

        // pass A: per-row max of raw U_K
        float lmax = -INFINITY;
#pragma unroll
        for (int m = 0; m < 2; m++) {
            const int r1 = (wr * 2 + m) * 16 + (lane >> 2);
            float mx1 = -INFINITY, mx2 = -INFINITY;
#pragma unroll
            for (int jn = 0; jn < 8; jn++) {
                mx1 = fmaxf(mx1, fmaxf(acc[m][jn][0], acc[m][jn][1]));
                mx2 = fmaxf(mx2, fmaxf(acc[m][jn][2], acc[m][jn][3]));
            }
            mx1 = grp_max(mx1); mx2 = grp_max(mx2);
            lmax = fmaxf(lmax, fmaxf(mx1, mx2));
            if ((lane & 3) == 0) {
                rmarr[r1 * 4 + wc] = mx1;
                rmarr[(r1 + 8) * 4 + wc] = mx2;
            }
        }
#pragma unroll
        for (int o = 16; o; o >>= 1)
            lmax = fmaxf(lmax, __shfl_xor_sync(0xffffffffu, lmax, o));
        if (lane == 0) atomicMax(bmax, f2u(lmax));
        __syncthreads();

        // pass B: E' = exp(u - h - srow) via fexp, colsums += E'*exp(srow)
        float colp[16];
#pragma unroll
        for (int t = 0; t < 16; t++) colp[t] = 0.f;
#pragma unroll
        for (int m = 0; m < 2; m++)
#pragma unroll
            for (int half = 0; half < 2; half++) {
                const int row = (wr * 2 + m) * 16 + (lane >> 2) + 8 * half;
                const float s_r = fmaxf(fmaxf(rmarr[row * 4], rmarr[row * 4 + 1]),
                                        fmaxf(rmarr[row * 4 + 2], rmarr[row * 4 + 3]));
                const float hv = hrow[row];
                const float erm = __expf(s_r);
                const size_t ub =
                    (((size_t)tile * 2 + m) * 8 + wid) * 512 + half * 256 + lane;
#pragma unroll
                for (int jn = 0; jn < 8; jn++) {
                    const float E0 = fexp(acc[m][jn][half * 2]     - hv - s_r);
                    const float E1 = fexp(acc[m][jn][half * 2 + 1] - hv - s_r);
                    colp[jn * 2]     += E0 * erm;
                    colp[jn * 2 + 1] += E1 * erm;
                    g_E2[ub + jn * 32u] = __floats2half2_rn(E0, E1);
                }
                if ((lane & 3) == 0) g_srow[row0 + row] = s_r;
            }
#pragma unroll
        for (int t = 0; t < 16; t++) {
            float s = colp[t];
            s += __shfl_xor_sync(0xffffffffu, s, 4);
            s += __shfl_xor_sync(0xffffffffu, s, 8);
            s += __shfl_xor_sync(0xffffffffu, s, 16);
            colp[t] = s;
        }
        if (lane < 4) {
#pragma unroll
            for (int t = 0; t < 16; t++)
                atomicAdd(&cs[wc * 64 + (t >> 1) * 8 + 2 * lane + (t & 1)], colp[t]);
        }
        __syncthreads();
    }
    if (tid < NF) atomicAdd(&g_sumKraw[tid], cs[tid]);
    if (tid == 0) atomicMax(&g_max_u, *bmax);
}

// ---------------- pass 2: Q GEMM + cached ek, scale V ---------------------------
__global__ void __launch_bounds__(NT, 2)
sp_final(const float* __restrict__ Qg, const float* __restrict__ V,
         const float* __restrict__ omg, float* __restrict__ out, int ntiles) {
    extern __shared__ float sh[];
    uint32_t* Bff = (uint32_t*)sh;
    uint32_t* Aff = Bff + BFF_U32;
    float* hq    = (float*)(Aff + AFF_U32);  // 64
    float* sKs   = hq + 64;                  // 256
    float* rmarr = sKs + NF;                 // 256
    float* red0  = rmarr + 256;              // 256
    float* red1  = red0 + 256;               // 256
    float* red2  = red1 + 256;               // 256
    float* red3  = red2 + 256;               // 256
    float* scal  = red3 + 256;               // 64
    float* ssum  = scal + 64;                // 1

    const int tid = threadIdx.x, wid = tid >> 5, lane = tid & 31;
    const int wr = wid >> 2, wc = wid & 3;
    const float gm = g_maxval;

    load_B_h(omg, Bff, tid);
    if (tid < NF) sKs[tid] = g_sumK[tid];
    __syncthreads();
    if (tid == 0) {
        float s = 0.f;
        for (int j = 0; j < NF; j++) s += sKs[j];
        *ssum = s;
    }
    __syncthreads();
    const float ssv = *ssum;

    float acc[2][8][4];
    for (int tile = blockIdx.x; tile < ntiles; tile += gridDim.x) {
        const size_t row0 = (size_t)tile * 64;
#pragma unroll
        for (int t = 0; t < 8; t++) {
            const int i = tid + t * NT;
            const int sr = i >> 5;
            float4 v = *(const float4*)(Qg + (row0 + sr) * KD + (lane << 2));
            float p = v.x * v.x + v.y * v.y + v.z * v.z + v.w * v.w;
#pragma unroll
            for (int o = 16; o; o >>= 1) p += __shfl_xor_sync(0xffffffffu, p, o);
            if (lane == 0) hq[sr] = p * HC;
            frag_store(Aff, sr, lane, v);
        }
        __syncthreads();
        gemm_tile((const uint4*)Aff, (const uint4*)Bff, wr, wc, lane, acc);

        // pass A: per-row max of raw U_Q
#pragma unroll
        for (int m = 0; m < 2; m++) {
            const int r1 = (wr * 2 + m) * 16 + (lane >> 2);
            float mx1 = -INFINITY, mx2 = -INFINITY;
#pragma unroll
            for (int jn = 0; jn < 8; jn++) {
                mx1 = fmaxf(mx1, fmaxf(acc[m][jn][0], acc[m][jn][1]));
                mx2 = fmaxf(mx2, fmaxf(acc[m][jn][2], acc[m][jn][3]));
            }
            mx1 = grp_max(mx1); mx2 = grp_max(mx2);
            if ((lane & 3) == 0) {
                rmarr[r1 * 4 + wc] = mx1;
                rmarr[(r1 + 8) * 4 + wc] = mx2;
            }
        }
        __syncthreads();

        // pass B: W, S2, S3, T using cached ek; eq via fexp
#pragma unroll
        for (int m = 0; m < 2; m++)
#pragma unroll
            for (int half = 0; half < 2; half++) {
                const int row = (wr * 2 + m) * 16 + (lane >> 2) + 8 * half;
                const float rmv = fmaxf(fmaxf(rmarr[row * 4], rmarr[row * 4 + 1]),
                                        fmaxf(rmarr[row * 4 + 2], rmarr[row * 4 + 3]));
                const float subq = hq[row] + rmv;
                const float eksc = __expf(g_srow[row0 + row] - gm);
                const size_t ub =
                    (((size_t)tile * 2 + m) * 8 + wid) * 512 + half * 256 + lane;
                float W = 0.f, S2 = 0.f, S3 = 0.f, T = 0.f;
#pragma unroll
                for (int jn = 0; jn < 8; jn++) {
                    const __half2 e2 = g_E2[ub + jn * 32u];
                    const float2 ef = __half22float2(e2);
                    const float ek0 = ef.x * eksc, ek1 = ef.y * eksc;
                    const float eq0 = fexp(acc[m][jn][half * 2]     - subq);
                    const float eq1 = fexp(acc[m][jn][half * 2 + 1] - subq);
                    const int col0 = wc * 64 + jn * 8 + 2 * (lane & 3);
                    W  = fmaf(eq0, ek0, W);
                    W  = fmaf(eq1, ek1, W);
                    S2 += eq0 + eq1;
                    S3 += ek0 + ek1;
                    T  = fmaf(eq0, sKs[col0], T);
                    T  = fmaf(eq1, sKs[col0 + 1], T);
                }
                W = grp_sum(W); S2 = grp_sum(S2); S3 = grp_sum(S3); T = grp_sum(T);
                if ((lane & 3) == 0) {
                    red0[row * 4 + wc] = W;  red1[row * 4 + wc] = S2;
                    red2[row * 4 + wc] = S3; red3[row * 4 + wc] = T;
                }
            }
        __syncthreads();
        if (tid < 64) {
            const float W  = red0[tid * 4] + red0[tid * 4 + 1] + red0[tid * 4 + 2] + red0[tid * 4 + 3];
            const float S2 = red1[tid * 4] + red1[tid * 4 + 1] + red1[tid * 4 + 2] + red1[tid * 4 + 3];
            const float S3 = red2[tid * 4] + red2[tid * 4 + 1] + red2[tid * 4 + 2] + red2[tid * 4 + 3];
            const float T  = red3[tid * 4] + red3[tid * 4 + 1] + red3[tid * 4 + 2] + red3[tid * 4 + 3];
            const float w  = (W + 1e-4f * (S2 + S3) + 2.56e-6f) * (1.f / 256.f);
            const float nm = (T + 1e-4f * ssv) * 0.0625f + 1e-8f;
            scal[tid] = w / nm;
        }
        __syncthreads();

        const float4* Vg = (const float4*)(V + row0 * KD);
        float4* Og = (float4*)(out + row0 * KD);
#pragma unroll
        for (int t = 0; t < 8; t++) {
            const int i = tid + t * NT;
            const float s = scal[i >> 5];
            float4 v = Vg[i];
            v.x *= s; v.y *= s; v.z *= s; v.w *= s;
            Og[i] = v;
        }
        __syncthreads();
    }
}

// --------------------------------- host -----------------------------------------
extern "C" void kernel_launch(void* const* d_in, const int* in_sizes, int n_in,
                              void* d_out, int out_size) {
    const float* Q   = (const float*)d_in[0];
    const float* K   = (const float*)d_in[1];
    const float* V   = (const float*)d_in[2];
    const float* omg = (const float*)d_in[3];
    float* out = (float*)d_out;

    const int N = in_sizes[0] / KD;
    const int ntiles = N / 64;

    int dev = 0, sms = 148;
    cudaGetDevice(&dev);
    cudaDeviceGetAttribute(&sms, cudaDevAttrMultiProcessorCount, dev);
    const int grid = 2 * sms < ntiles ? 2 * sms : ntiles;

    const size_t smK = (size_t)(BFF_U32 + AFF_U32) * 4 +
                       (size_t)(64 + NF + 256 + 4) * sizeof(float);
    const size_t smF = (size_t)(BFF_U32 + AFF_U32) * 4 +
                       (size_t)(64 + NF + 256 + 256 * 4 + 64 + 8) * sizeof(float);
    cudaFuncSetAttribute(sp_kpass, cudaFuncAttributeMaxDynamicSharedMemorySize, (int)smK);
    cudaFuncSetAttribute(sp_final, cudaFuncAttributeMaxDynamicSharedMemorySize, (int)smF);

    sp_init<<<1, NF>>>();
    sp_kpass<<<grid, NT, smK>>>(K, omg, ntiles);
    sp_finalize<<<1, NF>>>((float)N * 1e-4f);
    sp_final<<<grid, NT, smF>>>(Q, V, omg, out, ntiles);
}

// round 14
// speedup vs baseline: 1.0347x; 1.0347x over previous
#include <cuda_runtime.h>
#include <cuda_fp16.h>
#include <math.h>
#include <stdint.h>

#define NT     256
#define NF     256
#define KD     128
#define NMAX   262144

#define INVD4  0.2973017787506803f    // 128^(-1/4)
#define HC     0.04419417382415922f   // 1/(2*sqrt(128))

#define BFF_U32 16384                 // B fragments (fp16): 64 KB
#define AFF_U32 4096                  // A fragments (fp16, 64 phys rows): 16 KB

// ---------------- globals -------------------------------------------------------
static __device__ unsigned g_max_u;
static __device__ float    g_maxval;
static __device__ float    g_sumKraw[NF];
static __device__ float    g_sumK[NF];
static __device__ float    g_srow[NMAX];             // per-row max of raw U_K
// E' = exp(U_K - h - srow), per-thread contiguous:
// u32 idx = ((((tile*2 + m)*8 + wid)*2 + half)*32 + lane)*8 + jn
static __device__ __half2  g_E2[(size_t)NMAX * 128];

__device__ __forceinline__ unsigned f2u(float f) {
    unsigned b = __float_as_uint(f);
    return (b & 0x80000000u) ? ~b : (b | 0x80000000u);
}
__device__ __forceinline__ float u2f(unsigned u) {
    return (u & 0x80000000u) ? __uint_as_float(u ^ 0x80000000u) : __uint_as_float(~u);
}

__global__ void sp_init() {
    if (threadIdx.x == 0) g_max_u = 0u;
    g_sumKraw[threadIdx.x] = 0.f;
}
__global__ void sp_finalize(float neps) {
    const float gmax = u2f(g_max_u);
    if (threadIdx.x == 0) g_maxval = gmax;
    g_sumK[threadIdx.x] = (g_sumKraw[threadIdx.x] * expf(-gmax) + neps) * 0.0625f;
}

// ---------------- fp16 mma machinery --------------------------------------------
__device__ __forceinline__ void mma_f16(float* d, const uint4& a, uint32_t b0, uint32_t b1) {
    asm volatile(
        "mma.sync.aligned.m16n8k16.row.col.f32.f16.f16.f32 "
        "{%0,%1,%2,%3}, {%4,%5,%6,%7}, {%8,%9}, {%0,%1,%2,%3};\n"
        : "+f"(d[0]), "+f"(d[1]), "+f"(d[2]), "+f"(d[3])
        : "r"(a.x), "r"(a.y), "r"(a.z), "r"(a.w), "r"(b0), "r"(b1));
}

__device__ __forceinline__ void load_B_h(const float* __restrict__ omg,
                                         uint32_t* __restrict__ Bff, int tid) {
    __half* Bh = (__half*)Bff;
    for (int i = tid; i < KD * NF; i += NT) {
        const int k = i >> 8, n = i & 255;
        const __half hv = __float2half(omg[i] * INVD4);
        const int np = n >> 3, npair = np >> 1, ks = k >> 4;
        const int lane = ((n & 7) << 2) | ((k & 7) >> 1);
        const int slot = ((np & 1) << 1) | ((k >> 3) & 1);
        const int u32idx = ((npair * 8 + ks) * 32 + lane) * 4 + slot;
        Bh[u32idx * 2 + (k & 1)] = hv;
    }
}

__device__ __forceinline__ void frag_store(uint32_t* __restrict__ Aff, int sr, int lane,
                                           const float4& v) {
    __half2 h01 = __floats2half2_rn(v.x, v.y);
    __half2 h23 = __floats2half2_rn(v.z, v.w);
    const int k0 = lane << 2;
    const int mi = sr >> 4, rlo = sr & 15, ks = k0 >> 4;
    const int reg = ((rlo >> 3) & 1) | (((k0 >> 3) & 1) << 1);
    const int ls  = ((rlo & 7) << 2) | ((k0 >> 1) & 3);
    uint32_t* base = Aff + (unsigned)((mi * 8 + ks) * 32) * 4 + reg;
    base[ls * 4]       = *(uint32_t*)&h01;
    base[(ls + 1) * 4] = *(uint32_t*)&h23;
}

// 64x256x128 GEMM, 8 warps, warp (wr,wc) owns 32 phys rows x 64 cols
__device__ __forceinline__ void gemm_tile(const uint4* __restrict__ Aff4,
                                          const uint4* __restrict__ Bff4,
                                          int wr, int wc, int lane, float acc[2][8][4]) {
#pragma unroll
    for (int i = 0; i < 2; i++)
#pragma unroll
        for (int j = 0; j < 8; j++)
#pragma unroll
            for (int c = 0; c < 4; c++) acc[i][j][c] = 0.f;
#pragma unroll
    for (int ks = 0; ks < 8; ks++) {
        uint4 a0 = Aff4[((wr * 2) * 8 + ks) * 32 + lane];
        uint4 a1 = Aff4[((wr * 2 + 1) * 8 + ks) * 32 + lane];
#pragma unroll
        for (int p = 0; p < 4; p++) {
            uint4 bv = Bff4[((wc * 4 + p) * 8 + ks) * 32 + lane];
            mma_f16(acc[0][2 * p],     a0, bv.x, bv.y);
            mma_f16(acc[0][2 * p + 1], a0, bv.z, bv.w);
            mma_f16(acc[1][2 * p],     a1, bv.x, bv.y);
            mma_f16(acc[1][2 * p + 1], a1, bv.z, bv.w);
        }
    }
}

__device__ __forceinline__ float grp_sum(float v) {
    v += __shfl_xor_sync(0xffffffffu, v, 1);
    v += __shfl_xor_sync(0xffffffffu, v, 2);
    return v;
}
__device__ __forceinline__ float grp_max(float v) {
    v = fmaxf(v, __shfl_xor_sync(0xffffffffu, v, 1));
    v = fmaxf(v, __shfl_xor_sync(0xffffffffu, v, 2));
    return v;
}

// ---------------- pass 1: U_K -> gmax, colsums, E' cache ------------------------
__global__ void __launch_bounds__(NT, 2)
sp_kpass(const float* __restrict__ Kg, const float* __restrict__ omg, int ntiles) {
    extern __shared__ float sh[];
    uint32_t* Bff = (uint32_t*)sh;
    uint32_t* Aff = Bff + BFF_U32;
    float* hrow  = (float*)(Aff + AFF_U32);  // 64
    float* cs    = hrow + 64;                // 256
    float* rmarr = cs + NF;                  // 256
    unsigned* bmax = (unsigned*)(rmarr + 256);

    const int tid = threadIdx.x, wid = tid >> 5, lane = tid & 31;
    const int wr = wid >> 2, wc = wid & 3;

    load_B_h(omg, Bff, tid);
    if (tid < NF) cs[tid] = 0.f;
    if (tid == 0) *bmax = 0u;
    __syncthreads();

    float acc[2][8][4];
    for (int tile = blockIdx.x; tile < ntiles; tile += gridDim.x) {
        const size_t row0 = (size_t)tile * 64;
#pragma unroll
        for (int t = 0; t < 8; t++) {
            const int i = tid + t * NT;
            const int sr = i >> 5;
            float4 v = *(const float4*)(Kg + (row0 + sr) * KD + (lane << 2));
            float p = v.x * v.x + v.y * v.y + v.z * v.z + v.w * v.w;
#pragma unroll
            for (int o = 16; o; o >>= 1) p += __shfl_xor_sync(0xffffffffu, p, o);
            if (lane == 0) hrow[sr] = p * HC;
            frag_store(Aff, sr, lane, v);
        }
        __syncthreads();
        gemm_tile((const uint4*)Aff, (const uint4*)Bff, wr, wc, lane, acc);

        // pass A: per-row max of raw U_K
        float lmax = -INFINITY;
#pragma unroll
        for (int m = 0; m < 2; m++) {
            const int r1 = (wr * 2 + m) * 16 + (lane >> 2);
            float mx1 = -INFINITY, mx2 = -INFINITY;
#pragma unroll
            for (int jn = 0; jn < 8; jn++) {
                mx1 = fmaxf(mx1, fmaxf(acc[m][jn][0], acc[m][jn][1]));
                mx2 = fmaxf(mx2, fmaxf(acc[m][jn][2], acc[m][jn][3]));
            }
            mx1 = grp_max(mx1); mx2 = grp_max(mx2);
            lmax = fmaxf(lmax, fmaxf(mx1, mx2));
            if ((lane & 3) == 0) {
                rmarr[r1 * 4 + wc] = mx1;
                rmarr[(r1 + 8) * 4 + wc] = mx2;
            }
        }
#pragma unroll
        for (int o = 16; o; o >>= 1)
            lmax = fmaxf(lmax, __shfl_xor_sync(0xffffffffu, lmax, o));
        if (lane == 0) atomicMax(bmax, f2u(lmax));
        __syncthreads();

        // pass B: E' = exp(u - h - srow), colsums += E'*exp(srow), vector store E'
        float colp[16];
#pragma unroll
        for (int t = 0; t < 16; t++) colp[t] = 0.f;
#pragma unroll
        for (int m = 0; m < 2; m++)
#pragma unroll
            for (int half = 0; half < 2; half++) {
                const int row = (wr * 2 + m) * 16 + (lane >> 2) + 8 * half;
                const float s_r = fmaxf(fmaxf(rmarr[row * 4], rmarr[row * 4 + 1]),
                                        fmaxf(rmarr[row * 4 + 2], rmarr[row * 4 + 3]));
                const float hv = hrow[row];
                const float erm = __expf(s_r);
                uint32_t e2loc[8];
#pragma unroll
                for (int jn = 0; jn < 8; jn++) {
                    const float E0 = __expf(acc[m][jn][half * 2]     - hv - s_r);
                    const float E1 = __expf(acc[m][jn][half * 2 + 1] - hv - s_r);
                    colp[jn * 2]     += E0 * erm;
                    colp[jn * 2 + 1] += E1 * erm;
                    __half2 h2 = __floats2half2_rn(E0, E1);
                    e2loc[jn] = *(uint32_t*)&h2;
                }
                const size_t base =
                    (((((size_t)tile * 2 + m) * 8 + wid) * 2 + half) * 32 + lane) * 8;
                uint4* dst = (uint4*)((uint32_t*)g_E2 + base);
                dst[0] = ((uint4*)e2loc)[0];
                dst[1] = ((uint4*)e2loc)[1];
                if ((lane & 3) == 0) g_srow[row0 + row] = s_r;
            }
#pragma unroll
        for (int t = 0; t < 16; t++) {
            float s = colp[t];
            s += __shfl_xor_sync(0xffffffffu, s, 4);
            s += __shfl_xor_sync(0xffffffffu, s, 8);
            s += __shfl_xor_sync(0xffffffffu, s, 16);
            colp[t] = s;
        }
        if (lane < 4) {
#pragma unroll
            for (int t = 0; t < 16; t++)
                atomicAdd(&cs[wc * 64 + (t >> 1) * 8 + 2 * lane + (t & 1)], colp[t]);
        }
        __syncthreads();
    }
    if (tid < NF) atomicAdd(&g_sumKraw[tid], cs[tid]);
    if (tid == 0) atomicMax(&g_max_u, *bmax);
}

// ---------------- pass 2: Q GEMM + cached ek, scale V ---------------------------
__global__ void __launch_bounds__(NT, 2)
sp_final(const float* __restrict__ Qg, const float* __restrict__ V,
         const float* __restrict__ omg, float* __restrict__ out, int ntiles) {
    extern __shared__ float sh[];
    uint32_t* Bff = (uint32_t*)sh;
    uint32_t* Aff = Bff + BFF_U32;
    float* hq    = (float*)(Aff + AFF_U32);  // 64
    float* srw   = hq + 64;                  // 64
    float* sKs   = srw + 64;                 // 256
    float* rmarr = sKs + NF;                 // 256
    float* red0  = rmarr + 256;              // 256
    float* red1  = red0 + 256;               // 256
    float* red2  = red1 + 256;               // 256
    float* red3  = red2 + 256;               // 256
    float* scal  = red3 + 256;               // 64
    float* ssum  = scal + 64;                // 1

    const int tid = threadIdx.x, wid = tid >> 5, lane = tid & 31;
    const int wr = wid >> 2, wc = wid & 3;
    const float gm = g_maxval;

    load_B_h(omg, Bff, tid);
    if (tid < NF) sKs[tid] = g_sumK[tid];
    __syncthreads();
    if (tid == 0) {
        float s = 0.f;
        for (int j = 0; j < NF; j++) s += sKs[j];
        *ssum = s;
    }
    __syncthreads();
    const float ssv = *ssum;

    float acc[2][8][4];
    for (int tile = blockIdx.x; tile < ntiles; tile += gridDim.x) {
        const size_t row0 = (size_t)tile * 64;
        if (tid < 64) srw[tid] = g_srow[row0 + tid];
#pragma unroll
        for (int t = 0; t < 8; t++) {
            const int i = tid + t * NT;
            const int sr = i >> 5;
            float4 v = *(const float4*)(Qg + (row0 + sr) * KD + (lane << 2));
            float p = v.x * v.x + v.y * v.y + v.z * v.z + v.w * v.w;
#pragma unroll
            for (int o = 16; o; o >>= 1) p += __shfl_xor_sync(0xffffffffu, p, o);
            if (lane == 0) hq[sr] = p * HC;
            frag_store(Aff, sr, lane, v);
        }
        __syncthreads();
        gemm_tile((const uint4*)Aff, (const uint4*)Bff, wr, wc, lane, acc);

        // pass A: per-row max of raw U_Q
#pragma unroll
        for (int m = 0; m < 2; m++) {
            const int r1 = (wr * 2 + m) * 16 + (lane >> 2);
            float mx1 = -INFINITY, mx2 = -INFINITY;
#pragma unroll
            for (int jn = 0; jn < 8; jn++) {
                mx1 = fmaxf(mx1, fmaxf(acc[m][jn][0], acc[m][jn][1]));
                mx2 = fmaxf(mx2, fmaxf(acc[m][jn][2], acc[m][jn][3]));
            }
            mx1 = grp_max(mx1); mx2 = grp_max(mx2);
            if ((lane & 3) == 0) {
                rmarr[r1 * 4 + wc] = mx1;
                rmarr[(r1 + 8) * 4 + wc] = mx2;
            }
        }
        __syncthreads();

        // pass B: W, S2, S3, T using cached ek (vector loads)
#pragma unroll
        for (int m = 0; m < 2; m++)
#pragma unroll
            for (int half = 0; half < 2; half++) {
                const int row = (wr * 2 + m) * 16 + (lane >> 2) + 8 * half;
                const float rmv = fmaxf(fmaxf(rmarr[row * 4], rmarr[row * 4 + 1]),
                                        fmaxf(rmarr[row * 4 + 2], rmarr[row * 4 + 3]));
                const float subq = hq[row] + rmv;
                const float eksc = __expf(srw[row] - gm);
                const size_t base =
                    (((((size_t)tile * 2 + m) * 8 + wid) * 2 + half) * 32 + lane) * 8;
                const uint4* src = (const uint4*)((const uint32_t*)g_E2 + base);
                uint32_t e2loc[8];
                ((uint4*)e2loc)[0] = src[0];
                ((uint4*)e2loc)[1] = src[1];
                float W = 0.f, S2 = 0.f, S3 = 0.f, T = 0.f;
#pragma unroll
                for (int jn = 0; jn < 8; jn++) {
                    const float2 ef = __half22float2(*reinterpret_cast<__half2*>(&e2loc[jn]));
                    const float ek0 = ef.x * eksc, ek1 = ef.y * eksc;
                    const float eq0 = __expf(acc[m][jn][half * 2]     - subq);
                    const float eq1 = __expf(acc[m][jn][half * 2 + 1] - subq);
                    const int col0 = wc * 64 + jn * 8 + 2 * (lane & 3);
                    W  = fmaf(eq0, ek0, W);
                    W  = fmaf(eq1, ek1, W);
                    S2 += eq0 + eq1;
                    S3 += ek0 + ek1;
                    T  = fmaf(eq0, sKs[col0], T);
                    T  = fmaf(eq1, sKs[col0 + 1], T);
                }
                W = grp_sum(W); S2 = grp_sum(S2); S3 = grp_sum(S3); T = grp_sum(T);
                if ((lane & 3) == 0) {
                    red0[row * 4 + wc] = W;  red1[row * 4 + wc] = S2;
                    red2[row * 4 + wc] = S3; red3[row * 4 + wc] = T;
                }
            }
        __syncthreads();
        if (tid < 64) {
            const float W  = red0[tid * 4] + red0[tid * 4 + 1] + red0[tid * 4 + 2] + red0[tid * 4 + 3];
            const float S2 = red1[tid * 4] + red1[tid * 4 + 1] + red1[tid * 4 + 2] + red1[tid * 4 + 3];
            const float S3 = red2[tid * 4] + red2[tid * 4 + 1] + red2[tid * 4 + 2] + red2[tid * 4 + 3];
            const float T  = red3[tid * 4] + red3[tid * 4 + 1] + red3[tid * 4 + 2] + red3[tid * 4 + 3];
            const float w  = (W + 1e-4f * (S2 + S3) + 2.56e-6f) * (1.f / 256.f);
            const float nm = (T + 1e-4f * ssv) * 0.0625f + 1e-8f;
            scal[tid] = w / nm;
        }
        __syncthreads();

        const float4* Vg = (const float4*)(V + row0 * KD);
        float4* Og = (float4*)(out + row0 * KD);
#pragma unroll
        for (int t = 0; t < 8; t++) {
            const int i = tid + t * NT;
            const float s = scal[i >> 5];
            float4 v = Vg[i];
            v.x *= s; v.y *= s; v.z *= s; v.w *= s;
            Og[i] = v;
        }
        __syncthreads();
    }
}

// --------------------------------- host -----------------------------------------
extern "C" void kernel_launch(void* const* d_in, const int* in_sizes, int n_in,
                              void* d_out, int out_size) {
    const float* Q   = (const float*)d_in[0];
    const float* K   = (const float*)d_in[1];
    const float* V   = (const float*)d_in[2];
    const float* omg = (const float*)d_in[3];
    float* out = (float*)d_out;

    const int N = in_sizes[0] / KD;
    const int ntiles = N / 64;

    int dev = 0, sms = 148;
    cudaGetDevice(&dev);
    cudaDeviceGetAttribute(&sms, cudaDevAttrMultiProcessorCount, dev);
    const int grid = 2 * sms < ntiles ? 2 * sms : ntiles;

    const size_t smK = (size_t)(BFF_U32 + AFF_U32) * 4 +
                       (size_t)(64 + NF + 256 + 4) * sizeof(float);
    const size_t smF = (size_t)(BFF_U32 + AFF_U32) * 4 +
                       (size_t)(64 + 64 + NF + 256 + 256 * 4 + 64 + 8) * sizeof(float);
    cudaFuncSetAttribute(sp_kpass, cudaFuncAttributeMaxDynamicSharedMemorySize, (int)smK);
    cudaFuncSetAttribute(sp_final, cudaFuncAttributeMaxDynamicSharedMemorySize, (int)smF);

    sp_init<<<1, NF>>>();
    sp_kpass<<<grid, NT, smK>>>(K, omg, ntiles);
    sp_finalize<<<1, NF>>>((float)N * 1e-4f);
    sp_final<<<grid, NT, smF>>>(Q, V, omg, out, ntiles);
}